// round 15
// baseline (speedup 1.0000x reference)
#include <cuda_runtime.h>
#include <cstdint>

#define CIN   80
#define COUT  32
#define BATCH 8
#define HH    160
#define WW    320
#define DD    48
#define HW    (HH*WW)      // 51200
#define RSTR  376          // padded R row stride: 48 zero + 320 + 8 (16B-mult)

typedef unsigned long long ull;

// feature scratch: [img][b][o][h][w]; L features pre-scaled by 1/32
__device__ float g_feat[2u * BATCH * COUT * HW];

__device__ __forceinline__ ull fma2(ull a, ull b, ull c) {
    ull d;
    asm("fma.rn.f32x2 %0, %1, %2, %3;" : "=l"(d) : "l"(a), "l"(b), "l"(c));
    return d;
}
__device__ __forceinline__ ull mul2(ull a, ull b) {
    ull d;
    asm("mul.rn.f32x2 %0, %1, %2;" : "=l"(d) : "l"(a), "l"(b));
    return d;
}
__device__ __forceinline__ ull pack2(float lo, float hi) {
    ull d;
    asm("mov.b64 %0, {%1, %2};" : "=l"(d) : "f"(lo), "f"(hi));
    return d;
}
__device__ __forceinline__ uint32_t s2u(const void* p) {
    uint32_t a;
    asm("{ .reg .u64 t; cvta.to.shared.u64 t, %1; cvt.u32.u64 %0, t; }" : "=r"(a) : "l"(p));
    return a;
}
__device__ __forceinline__ void bulk1d(uint32_t dst, const void* src, uint32_t bytes, uint32_t mbar) {
    asm volatile("cp.async.bulk.shared::cluster.global.mbarrier::complete_tx::bytes [%0], [%1], %2, [%3];"
                 :: "r"(dst), "l"(src), "r"(bytes), "r"(mbar) : "memory");
}
__device__ __forceinline__ void mbar_init(uint32_t mbar, uint32_t cnt) {
    asm volatile("mbarrier.init.shared.b64 [%0], %1;" :: "r"(mbar), "r"(cnt) : "memory");
}
__device__ __forceinline__ void mbar_expect(uint32_t mbar, uint32_t tx) {
    asm volatile("mbarrier.arrive.expect_tx.shared.b64 _, [%0], %1;" :: "r"(mbar), "r"(tx) : "memory");
}
__device__ __forceinline__ void mbar_wait(uint32_t mbar, uint32_t parity) {
    uint32_t done;
    asm volatile("{\n\t.reg .pred p;\n\t"
                 "mbarrier.try_wait.parity.acquire.cta.shared::cta.b64 p, [%1], %2;\n\t"
                 "selp.b32 %0, 1, 0, p;\n\t}" : "=r"(done) : "r"(mbar), "r"(parity) : "memory");
    while (!done) {
        asm volatile("{\n\t.reg .pred p;\n\t"
                     "mbarrier.try_wait.parity.acquire.cta.shared::cta.b64 p, [%1], %2, 0x989680;\n\t"
                     "selp.b32 %0, 1, 0, p;\n\t}" : "=r"(done) : "r"(mbar), "r"(parity) : "memory");
    }
}

// ===========================================================================
// K1: preconv (relu + folded BN + 1x1 conv). One block per (b,h,img) row.
// Thread = (u, og): float4 at col 4u, outputs og*8..og*8+7. 16 ull accs.
// smem = weights only; mainloop has no barriers. 3 CTAs/SM, 30 warps.
// ===========================================================================
__global__ __launch_bounds__(320, 3) void preconv_kernel(
    const float* __restrict__ inL, const float* __restrict__ inR,
    const float* __restrict__ bg,  const float* __restrict__ bb,
    const float* __restrict__ bm,  const float* __restrict__ bv,
    const float* __restrict__ cw,  const float* __restrict__ cb)
{
    __shared__ ull sW[CIN * COUT];   // splatted folded weights [80][32]
    __shared__ ull sB[COUT];

    const int tid = threadIdx.x;
    for (int idx = tid; idx < CIN * COUT; idx += 320) {
        int c = idx >> 5, o = idx & 31;
        float sc = bg[c] * rsqrtf(bv[c] + 1e-5f);
        float wv = cw[o * CIN + c] * sc;
        sW[idx] = pack2(wv, wv);
    }
    if (tid < COUT) {
        float s = cb[tid];
        for (int c = 0; c < CIN; c++) {
            float sc = bg[c] * rsqrtf(bv[c] + 1e-5f);
            s += cw[tid * CIN + c] * (bb[c] - bm[c] * sc);
        }
        sB[tid] = pack2(s, s);
    }
    __syncthreads();

    const int row = blockIdx.x;           // (bh, img)
    const int img = row & 1;
    const int bh  = row >> 1;
    const int h   = bh % HH, b = bh / HH;
    const float* in = img ? inR : inL;
    const float* p  = in + (long)b * CIN * HW + (long)h * WW + 4 * (tid % 80);
    const int og = tid / 80;              // 0..3

    ull a0[8], a1[8];
    #pragma unroll
    for (int oo = 0; oo < 8; oo++) { a0[oo] = sB[og * 8 + oo]; a1[oo] = a0[oo]; }

    #pragma unroll 4
    for (int c = 0; c < CIN; c++) {
        float4 xv = __ldg((const float4*)(p + (long)c * HW));
        ull x01 = pack2(fmaxf(xv.x, 0.f), fmaxf(xv.y, 0.f));
        ull x23 = pack2(fmaxf(xv.z, 0.f), fmaxf(xv.w, 0.f));
        const ulonglong2* wr = (const ulonglong2*)&sW[c * 32 + og * 8];
        #pragma unroll
        for (int j = 0; j < 4; j++) {
            ulonglong2 W2 = wr[j];         // broadcast LDS.128 (outs 2j, 2j+1)
            a0[2*j]   = fma2(x01, W2.x, a0[2*j]);
            a1[2*j]   = fma2(x23, W2.x, a1[2*j]);
            a0[2*j+1] = fma2(x01, W2.y, a0[2*j+1]);
            a1[2*j+1] = fma2(x23, W2.y, a1[2*j+1]);
        }
    }

    // L features carry the 1/32 correlation-mean factor
    if (img == 0) {
        const ull inv2 = pack2(0.03125f, 0.03125f);
        #pragma unroll
        for (int oo = 0; oo < 8; oo++) { a0[oo] = mul2(a0[oo], inv2); a1[oo] = mul2(a1[oo], inv2); }
    }
    float* outp = g_feat + (long)img * (BATCH * COUT * HW)
                + (long)b * COUT * HW + (long)h * WW + 4 * (tid % 80);
    #pragma unroll
    for (int oo = 0; oo < 8; oo++) {
        ulonglong2 v; v.x = a0[oo]; v.y = a1[oo];
        *(ulonglong2*)(outp + (long)(og * 8 + oo) * HW) = v;   // STG.128
    }
}

// ===========================================================================
// K2: correlation. One block per (b,h) row; features TMA-bulk'd into smem.
// Thread = (wq, ig): 2 pairs (4 w) x 12 disparities (R7-proven tile).
// smem: mbar(8) + Ls[32][320] + RA[32][376] = 89088 + pad -> 2 CTAs/SM.
// ===========================================================================
#define K2_SMEM (16 + (32*WW + 32*RSTR) * 4)   // 89104

__global__ __launch_bounds__(320, 2) void corr_kernel(float* __restrict__ out)
{
    extern __shared__ char smraw[];
    float* Ls = (float*)(smraw + 16);     // [32][320] (already scaled by 1/32)
    float* RA = Ls + 32 * WW;             // [32][376]; RA[o][j] = featR[o][j-48]
    const uint32_t mbar = s2u(smraw);

    const int tid = threadIdx.x;
    const int bh  = blockIdx.x;
    const int h   = bh % HH, b = bh / HH;
    const float* fL = g_feat + (long)b * COUT * HW + (long)h * WW;
    const float* fR = fL + (long)(BATCH * COUT) * HW;

    if (tid == 0) {
        mbar_init(mbar, 1);
        asm volatile("fence.proxy.async.shared::cta;" ::: "memory");
        mbar_expect(mbar, 64 * 1280);
        uint32_t lsb = s2u(Ls), rab = s2u(RA);
        for (int o = 0; o < 32; o++) {
            bulk1d(lsb + o * (WW * 4),            fL + (long)o * HW, 1280, mbar);
            bulk1d(rab + o * (RSTR * 4) + 192,    fR + (long)o * HW, 1280, mbar);
        }
    }
    // zero RA pads (cols [0,48) and [368,376)) while TMA is in flight
    for (int idx = tid; idx < 32 * 56; idx += 320) {
        int o = idx / 56, j = idx % 56;
        RA[o * RSTR + (j < 48 ? j : 320 + j)] = 0.f;
    }
    __syncthreads();
    mbar_wait(mbar, 0);

    const int wq = tid % 80, ig = tid / 80;
    const int W0 = 4 * wq;
    const int i0 = 12 * ig;

    ull aP[12], aQ[12];
    #pragma unroll
    for (int d = 0; d < 12; d++) { aP[d] = 0ULL; aQ[d] = 0ULL; }

    #pragma unroll 2
    for (int c = 0; c < 32; c++) {
        ulonglong2 Lp = *(const ulonglong2*)&Ls[c * WW + W0];
        const float* rr = &RA[c * RSTR + W0 + 36 - i0];
        ull V[8];
        #pragma unroll
        for (int m = 0; m < 4; m++) {
            ulonglong2 t = *(const ulonglong2*)&rr[4 * m];   // LDS.128
            V[2*m] = t.x; V[2*m+1] = t.y;
        }
        #pragma unroll
        for (int dd = 0; dd < 12; dd++) {
            ull v0, v1;
            if ((dd & 1) == 0) {
                v0 = V[(12 - dd) / 2];
                v1 = V[(14 - dd) / 2];
            } else {
                const float2* f11 = (const float2*)&V[(11 - dd) / 2];
                const float2* f13 = (const float2*)&V[(13 - dd) / 2];
                const float2* f15 = (const float2*)&V[(15 - dd) / 2];
                v0 = pack2(f11->y, f13->x);
                v1 = pack2(f13->y, f15->x);
            }
            aP[dd] = fma2(Lp.x, v0, aP[dd]);
            aQ[dd] = fma2(Lp.y, v1, aQ[dd]);
        }
    }

    float* outp = out + ((long)b * DD * HH + h) * WW;
    #pragma unroll
    for (int dd = 0; dd < 12; dd++) {
        float2 p = *(float2*)&aP[dd];
        float2 q = *(float2*)&aQ[dd];
        float4 v; v.x = p.x; v.y = p.y; v.z = q.x; v.w = q.y;
        *(float4*)&outp[(long)(i0 + dd) * HW + W0] = v;     // STG.128
    }
}

// ---------------------------------------------------------------------------
extern "C" void kernel_launch(void* const* d_in, const int* in_sizes, int n_in,
                              void* d_out, int out_size)
{
    const float* fL = (const float*)d_in[0];
    const float* fR = (const float*)d_in[1];
    const float* bg = (const float*)d_in[2];
    const float* bb = (const float*)d_in[3];
    const float* bm = (const float*)d_in[4];
    const float* bv = (const float*)d_in[5];
    const float* cw = (const float*)d_in[6];
    const float* cb = (const float*)d_in[7];
    float* out = (float*)d_out;

    cudaFuncSetAttribute(corr_kernel, cudaFuncAttributeMaxDynamicSharedMemorySize, K2_SMEM);
    preconv_kernel<<<2 * BATCH * HH, 320>>>(fL, fR, bg, bb, bm, bv, cw, cb);
    corr_kernel<<<BATCH * HH, 320, K2_SMEM>>>(out);
}

// round 16
// speedup vs baseline: 1.1867x; 1.1867x over previous
#include <cuda_runtime.h>
#include <cstdint>

#define CIN   80
#define COUT  32
#define BATCH 8
#define HH    160
#define WW    320
#define DD    48
#define HW    (HH*WW)      // 51200
#define RSTR  376          // padded R row stride: 48 zero + 320 + 8 (16B-mult)

typedef unsigned long long ull;

// feature scratch: [img][b][o][h][w]; L features pre-scaled by 1/32
__device__ float g_feat[2u * BATCH * COUT * HW];

__device__ __forceinline__ ull fma2(ull a, ull b, ull c) {
    ull d;
    asm("fma.rn.f32x2 %0, %1, %2, %3;" : "=l"(d) : "l"(a), "l"(b), "l"(c));
    return d;
}
__device__ __forceinline__ ull mul2(ull a, ull b) {
    ull d;
    asm("mul.rn.f32x2 %0, %1, %2;" : "=l"(d) : "l"(a), "l"(b));
    return d;
}
__device__ __forceinline__ ull pack2(float lo, float hi) {
    ull d;
    asm("mov.b64 %0, {%1, %2};" : "=l"(d) : "f"(lo), "f"(hi));
    return d;
}
__device__ __forceinline__ uint32_t s2u(const void* p) {
    uint32_t a;
    asm("{ .reg .u64 t; cvta.to.shared.u64 t, %1; cvt.u32.u64 %0, t; }" : "=r"(a) : "l"(p));
    return a;
}
__device__ __forceinline__ void bulk1d(uint32_t dst, const void* src, uint32_t bytes, uint32_t mbar) {
    asm volatile("cp.async.bulk.shared::cluster.global.mbarrier::complete_tx::bytes [%0], [%1], %2, [%3];"
                 :: "r"(dst), "l"(src), "r"(bytes), "r"(mbar) : "memory");
}
__device__ __forceinline__ void mbar_init(uint32_t mbar, uint32_t cnt) {
    asm volatile("mbarrier.init.shared.b64 [%0], %1;" :: "r"(mbar), "r"(cnt) : "memory");
}
__device__ __forceinline__ void mbar_expect(uint32_t mbar, uint32_t tx) {
    asm volatile("mbarrier.arrive.expect_tx.shared.b64 _, [%0], %1;" :: "r"(mbar), "r"(tx) : "memory");
}
__device__ __forceinline__ void mbar_wait(uint32_t mbar, uint32_t parity) {
    uint32_t done;
    asm volatile("{\n\t.reg .pred p;\n\t"
                 "mbarrier.try_wait.parity.acquire.cta.shared::cta.b64 p, [%1], %2;\n\t"
                 "selp.b32 %0, 1, 0, p;\n\t}" : "=r"(done) : "r"(mbar), "r"(parity) : "memory");
    while (!done) {
        asm volatile("{\n\t.reg .pred p;\n\t"
                     "mbarrier.try_wait.parity.acquire.cta.shared::cta.b64 p, [%1], %2, 0x989680;\n\t"
                     "selp.b32 %0, 1, 0, p;\n\t}" : "=r"(done) : "r"(mbar), "r"(parity) : "memory");
    }
}

// ===========================================================================
// K1: preconv, TMA-staged. One block per (b,h,img) row; 320 threads; 3 CTAs/SM.
// smem: sW[80][32] ull (20480) | sB[32] ull (256) | 2 mbar (16) |
//       staging 2 x (16 ch x 320 f) (2 x 20480)  => 61712 B.
// Thread = (u, og): float4 at col 4u, outputs og*8..og*8+7; 16 ull accs.
// ===========================================================================
#define K1_CHUNK  16
#define K1_NCHUNK 5
#define K1_BUF    (K1_CHUNK * WW * 4)      // 20480 B
#define K1_OFF_SB   20480
#define K1_OFF_MBAR 20736
#define K1_OFF_STG  20752
#define K1_SMEM   (K1_OFF_STG + 2 * K1_BUF)   // 61712

__global__ __launch_bounds__(320, 3) void preconv_kernel(
    const float* __restrict__ inL, const float* __restrict__ inR,
    const float* __restrict__ bg,  const float* __restrict__ bb,
    const float* __restrict__ bm,  const float* __restrict__ bv,
    const float* __restrict__ cw,  const float* __restrict__ cb)
{
    extern __shared__ char smraw[];
    ull*   sW    = (ull*)smraw;                     // [80][32] splatted
    ull*   sB    = (ull*)(smraw + K1_OFF_SB);       // [32]
    float* stage = (float*)(smraw + K1_OFF_STG);
    const uint32_t smbase = s2u(smraw);
    const uint32_t mb0 = smbase + K1_OFF_MBAR;

    const int tid = threadIdx.x;
    const int row = blockIdx.x;           // (bh, img)
    const int img = row & 1;
    const int bh  = row >> 1;
    const int h   = bh % HH, b = bh / HH;
    const float* in = img ? inR : inL;
    const float* rowbase = in + (long)b * CIN * HW + (long)h * WW;

    if (tid == 0) { mbar_init(mb0, 1); mbar_init(mb0 + 8, 1); }
    __syncthreads();

    if (tid == 0) {
        #pragma unroll
        for (int k = 0; k < 2; k++) {
            uint32_t mbar = mb0 + k * 8;
            mbar_expect(mbar, (uint32_t)K1_BUF);
            uint32_t dst = smbase + K1_OFF_STG + k * K1_BUF;
            const float* src = rowbase + (long)(k * K1_CHUNK) * HW;
            for (int cc = 0; cc < K1_CHUNK; cc++)
                bulk1d(dst + cc * 1280, src + (long)cc * HW, 1280, mbar);
        }
    }

    // fold BN into weights
    for (int idx = tid; idx < CIN * COUT; idx += 320) {
        int c = idx >> 5, o = idx & 31;
        float sc = bg[c] * rsqrtf(bv[c] + 1e-5f);
        float wv = cw[o * CIN + c] * sc;
        sW[idx] = pack2(wv, wv);
    }
    if (tid < COUT) {
        float s = cb[tid];
        for (int c = 0; c < CIN; c++) {
            float sc = bg[c] * rsqrtf(bv[c] + 1e-5f);
            s += cw[tid * CIN + c] * (bb[c] - bm[c] * sc);
        }
        sB[tid] = pack2(s, s);
    }
    __syncthreads();

    const int u  = tid % 80;
    const int og = tid / 80;              // 0..3

    ull a0[8], a1[8];
    #pragma unroll
    for (int oo = 0; oo < 8; oo++) { a0[oo] = sB[og * 8 + oo]; a1[oo] = a0[oo]; }

    for (int k = 0; k < K1_NCHUNK; k++) {
        const int s = k & 1;
        mbar_wait(mb0 + s * 8, (k >> 1) & 1);
        const float* bufD = stage + s * (K1_BUF / 4) + 4 * u;

        #pragma unroll 4
        for (int cc = 0; cc < K1_CHUNK; cc++) {
            float4 xv = *(const float4*)(bufD + cc * WW);           // LDS.128
            ull x01 = pack2(fmaxf(xv.x, 0.f), fmaxf(xv.y, 0.f));
            ull x23 = pack2(fmaxf(xv.z, 0.f), fmaxf(xv.w, 0.f));
            const ulonglong2* wr = (const ulonglong2*)&sW[(k * K1_CHUNK + cc) * 32 + og * 8];
            #pragma unroll
            for (int j = 0; j < 4; j++) {
                ulonglong2 W2 = wr[j];        // broadcast LDS.128 (outs 2j, 2j+1)
                a0[2*j]   = fma2(x01, W2.x, a0[2*j]);
                a1[2*j]   = fma2(x23, W2.x, a1[2*j]);
                a0[2*j+1] = fma2(x01, W2.y, a0[2*j+1]);
                a1[2*j+1] = fma2(x23, W2.y, a1[2*j+1]);
            }
        }
        __syncthreads();   // buffer s fully consumed by all warps
        if (tid == 0 && k + 2 < K1_NCHUNK) {
            int kn = k + 2;
            uint32_t mbar = mb0 + s * 8;
            mbar_expect(mbar, (uint32_t)K1_BUF);
            uint32_t dst = smbase + K1_OFF_STG + s * K1_BUF;
            const float* src = rowbase + (long)(kn * K1_CHUNK) * HW;
            for (int cc = 0; cc < K1_CHUNK; cc++)
                bulk1d(dst + cc * 1280, src + (long)cc * HW, 1280, mbar);
        }
    }

    // L features carry the 1/32 correlation-mean factor
    if (img == 0) {
        const ull inv2 = pack2(0.03125f, 0.03125f);
        #pragma unroll
        for (int oo = 0; oo < 8; oo++) { a0[oo] = mul2(a0[oo], inv2); a1[oo] = mul2(a1[oo], inv2); }
    }
    float* outp = g_feat + (long)img * (BATCH * COUT * HW)
                + (long)b * COUT * HW + (long)h * WW + 4 * u;
    #pragma unroll
    for (int oo = 0; oo < 8; oo++) {
        ulonglong2 v; v.x = a0[oo]; v.y = a1[oo];
        *(ulonglong2*)(outp + (long)(og * 8 + oo) * HW) = v;   // STG.128
    }
}

// ===========================================================================
// K2: correlation (byte-identical to R15 passing version).
// ===========================================================================
#define K2_SMEM (16 + (32*WW + 32*RSTR) * 4)   // 89104

__global__ __launch_bounds__(320, 2) void corr_kernel(float* __restrict__ out)
{
    extern __shared__ char smraw[];
    float* Ls = (float*)(smraw + 16);     // [32][320] (already scaled by 1/32)
    float* RA = Ls + 32 * WW;             // [32][376]; RA[o][j] = featR[o][j-48]
    const uint32_t mbar = s2u(smraw);

    const int tid = threadIdx.x;
    const int bh  = blockIdx.x;
    const int h   = bh % HH, b = bh / HH;
    const float* fL = g_feat + (long)b * COUT * HW + (long)h * WW;
    const float* fR = fL + (long)(BATCH * COUT) * HW;

    if (tid == 0) {
        mbar_init(mbar, 1);
        asm volatile("fence.proxy.async.shared::cta;" ::: "memory");
        mbar_expect(mbar, 64 * 1280);
        uint32_t lsb = s2u(Ls), rab = s2u(RA);
        for (int o = 0; o < 32; o++) {
            bulk1d(lsb + o * (WW * 4),         fL + (long)o * HW, 1280, mbar);
            bulk1d(rab + o * (RSTR * 4) + 192, fR + (long)o * HW, 1280, mbar);
        }
    }
    // zero RA pads (cols [0,48) and [368,376)) while TMA is in flight
    for (int idx = tid; idx < 32 * 56; idx += 320) {
        int o = idx / 56, j = idx % 56;
        RA[o * RSTR + (j < 48 ? j : 320 + j)] = 0.f;
    }
    __syncthreads();
    mbar_wait(mbar, 0);

    const int wq = tid % 80, ig = tid / 80;
    const int W0 = 4 * wq;
    const int i0 = 12 * ig;

    ull aP[12], aQ[12];
    #pragma unroll
    for (int d = 0; d < 12; d++) { aP[d] = 0ULL; aQ[d] = 0ULL; }

    #pragma unroll 2
    for (int c = 0; c < 32; c++) {
        ulonglong2 Lp = *(const ulonglong2*)&Ls[c * WW + W0];
        const float* rr = &RA[c * RSTR + W0 + 36 - i0];
        ull V[8];
        #pragma unroll
        for (int m = 0; m < 4; m++) {
            ulonglong2 t = *(const ulonglong2*)&rr[4 * m];   // LDS.128
            V[2*m] = t.x; V[2*m+1] = t.y;
        }
        #pragma unroll
        for (int dd = 0; dd < 12; dd++) {
            ull v0, v1;
            if ((dd & 1) == 0) {
                v0 = V[(12 - dd) / 2];
                v1 = V[(14 - dd) / 2];
            } else {
                const float2* f11 = (const float2*)&V[(11 - dd) / 2];
                const float2* f13 = (const float2*)&V[(13 - dd) / 2];
                const float2* f15 = (const float2*)&V[(15 - dd) / 2];
                v0 = pack2(f11->y, f13->x);
                v1 = pack2(f13->y, f15->x);
            }
            aP[dd] = fma2(Lp.x, v0, aP[dd]);
            aQ[dd] = fma2(Lp.y, v1, aQ[dd]);
        }
    }

    float* outp = out + ((long)b * DD * HH + h) * WW;
    #pragma unroll
    for (int dd = 0; dd < 12; dd++) {
        float2 p = *(float2*)&aP[dd];
        float2 q = *(float2*)&aQ[dd];
        float4 v; v.x = p.x; v.y = p.y; v.z = q.x; v.w = q.y;
        *(float4*)&outp[(long)(i0 + dd) * HW + W0] = v;     // STG.128
    }
}

// ---------------------------------------------------------------------------
extern "C" void kernel_launch(void* const* d_in, const int* in_sizes, int n_in,
                              void* d_out, int out_size)
{
    const float* fL = (const float*)d_in[0];
    const float* fR = (const float*)d_in[1];
    const float* bg = (const float*)d_in[2];
    const float* bb = (const float*)d_in[3];
    const float* bm = (const float*)d_in[4];
    const float* bv = (const float*)d_in[5];
    const float* cw = (const float*)d_in[6];
    const float* cb = (const float*)d_in[7];
    float* out = (float*)d_out;

    cudaFuncSetAttribute(preconv_kernel, cudaFuncAttributeMaxDynamicSharedMemorySize, K1_SMEM);
    cudaFuncSetAttribute(corr_kernel,    cudaFuncAttributeMaxDynamicSharedMemorySize, K2_SMEM);
    preconv_kernel<<<2 * BATCH * HH, 320, K1_SMEM>>>(fL, fR, bg, bb, bm, bv, cw, cb);
    corr_kernel<<<BATCH * HH, 320, K2_SMEM>>>(out);
}